// round 1
// baseline (speedup 1.0000x reference)
#include <cuda_runtime.h>
#include <math.h>

// Problem dims (fixed by the dataset)
#define Bb 8
#define Ll 4800
#define Hh 8
#define Dd 64
#define BH (Bb*Hh)          // 64
#define STRIDE_L (Hh*Dd)    // 512 floats between consecutive l for fixed (b,h)

// Phase-1 split of L
#define NSPLIT 10
#define CHUNK (Ll/NSPLIT)   // 480
#define NT (CHUNK/16)       // 30 tiles of 16 l's

// Phase-3 tiling
#define LT3 32
#define TILES_PER_BLOCK 5
#define LBLOCK (LT3*TILES_PER_BLOCK)  // 160
#define NLB (Ll/LBLOCK)               // 30

// Scratch (static __device__ — no allocation in kernel_launch)
__device__ float g_Gp[NSPLIT*BH*Dd*Dd];   // partial Gram matrices [split][bh][d][e]
__device__ float g_Nqp[NSPLIT*BH*Dd];     // partial sum-of-squares for q norms
__device__ float g_Nkp[NSPLIT*BH*Dd];     // partial sum-of-squares for k norms
__device__ float g_At[BH*Dd*Dd];          // combined softmax matrix, TRANSPOSED: At[e][c] = A[c][e]

// ---------------------------------------------------------------------------
// Phase 1: partial Gram G[d,e] = sum_l q[l,d]*k[l,e] over an L-chunk,
// plus partial sum-of-squares per d (for the L2 norms).
// Grid (BH, NSPLIT), 256 threads. Each thread computes a 4x4 output tile.
// ---------------------------------------------------------------------------
__global__ __launch_bounds__(256) void phase1_kernel(const float* __restrict__ q,
                                                     const float* __restrict__ k)
{
    const int bh = blockIdx.x, sp = blockIdx.y;
    const int b = bh >> 3, h = bh & 7;
    const int tid = threadIdx.x;
    const int tx = tid & 15;       // e-group (4 cols)
    const int ty = tid >> 4;       // d-group (4 rows); also l-row for loads

    __shared__ float qs[16*64];
    __shared__ float ks[16*64];

    float acc[4][4];
#pragma unroll
    for (int i = 0; i < 4; i++)
#pragma unroll
        for (int j = 0; j < 4; j++) acc[i][j] = 0.f;

    float sq[4] = {0.f,0.f,0.f,0.f};
    float sk[4] = {0.f,0.f,0.f,0.f};

    const float* qb = q + (size_t)b*Ll*STRIDE_L + h*Dd;
    const float* kb = k + (size_t)b*Ll*STRIDE_L + h*Dd;
    const int l0 = sp*CHUNK;

    for (int t = 0; t < NT; t++) {
        const size_t loff = (size_t)(l0 + t*16 + ty)*STRIDE_L + tx*4;
        float4 vq = *(const float4*)(qb + loff);
        float4 vk = *(const float4*)(kb + loff);
        *(float4*)&qs[ty*64 + tx*4] = vq;
        *(float4*)&ks[ty*64 + tx*4] = vk;
        sq[0] += vq.x*vq.x; sq[1] += vq.y*vq.y; sq[2] += vq.z*vq.z; sq[3] += vq.w*vq.w;
        sk[0] += vk.x*vk.x; sk[1] += vk.y*vk.y; sk[2] += vk.z*vk.z; sk[3] += vk.w*vk.w;
        __syncthreads();
#pragma unroll
        for (int ll = 0; ll < 16; ll++) {
            float4 a  = *(const float4*)&qs[ll*64 + ty*4];
            float4 bb = *(const float4*)&ks[ll*64 + tx*4];
            acc[0][0] += a.x*bb.x; acc[0][1] += a.x*bb.y; acc[0][2] += a.x*bb.z; acc[0][3] += a.x*bb.w;
            acc[1][0] += a.y*bb.x; acc[1][1] += a.y*bb.y; acc[1][2] += a.y*bb.z; acc[1][3] += a.y*bb.w;
            acc[2][0] += a.z*bb.x; acc[2][1] += a.z*bb.y; acc[2][2] += a.z*bb.z; acc[2][3] += a.z*bb.w;
            acc[3][0] += a.w*bb.x; acc[3][1] += a.w*bb.y; acc[3][2] += a.w*bb.z; acc[3][3] += a.w*bb.w;
        }
        __syncthreads();
    }

    float* G = g_Gp + (size_t)(sp*BH + bh)*4096;
#pragma unroll
    for (int i = 0; i < 4; i++) {
        float4 r = make_float4(acc[i][0], acc[i][1], acc[i][2], acc[i][3]);
        *(float4*)&G[(ty*4 + i)*64 + tx*4] = r;
    }

    // Reduce the per-thread sum-of-squares (16 l-rows share each d-group)
    __syncthreads();
    *(float4*)&qs[ty*64 + tx*4] = make_float4(sq[0], sq[1], sq[2], sq[3]);
    *(float4*)&ks[ty*64 + tx*4] = make_float4(sk[0], sk[1], sk[2], sk[3]);
    __syncthreads();
    if (tid < 64) {
        float s1 = 0.f, s2 = 0.f;
#pragma unroll
        for (int r = 0; r < 16; r++) { s1 += qs[r*64 + tid]; s2 += ks[r*64 + tid]; }
        g_Nqp[(sp*BH + bh)*64 + tid] = s1;
        g_Nkp[(sp*BH + bh)*64 + tid] = s2;
    }
}

// ---------------------------------------------------------------------------
// Phase 2: per (b,h): assemble G, normalize (attn), gates, temperature,
// 4 top-k masked softmaxes fused into one A_total matrix, stored transposed.
// Top-k membership: x_e >= (k-th largest)  <=>  #{f: x_f > x_e} < k
// (ties included — exactly matching the reference's `attn >= thr`).
// Grid BH, 256 threads (4 threads per row in the top-k section).
// ---------------------------------------------------------------------------
__global__ __launch_bounds__(256) void phase2_kernel(
    const float* __restrict__ temp, const float* __restrict__ attns,
    const float* __restrict__ row_w, const float* __restrict__ row_b,
    const float* __restrict__ col_w, const float* __restrict__ col_b)
{
    const int bh = blockIdx.x;
    const int h  = bh & 7;
    const int tid = threadIdx.x;

    __shared__ float X[64*65];
    __shared__ float EX[64*65];
    __shared__ unsigned char CNT[64*64];
    __shared__ float nq[64], nk[64], wcol[64], wrow[64], rmax[64];
    __shared__ float pmax[64][4];
    __shared__ float zps[64][4][4];
    __shared__ float coef[64][4];

    // A. sum Gram partials over splits
    for (int idx = tid; idx < 4096; idx += 256) {
        float s = 0.f;
#pragma unroll
        for (int sp = 0; sp < NSPLIT; sp++) s += g_Gp[(size_t)(sp*BH + bh)*4096 + idx];
        X[(idx >> 6)*65 + (idx & 63)] = s;
    }
    if (tid < 64) {
        float s1 = 0.f, s2 = 0.f;
#pragma unroll
        for (int sp = 0; sp < NSPLIT; sp++) {
            s1 += g_Nqp[(sp*BH + bh)*64 + tid];
            s2 += g_Nkp[(sp*BH + bh)*64 + tid];
        }
        nq[tid] = fmaxf(sqrtf(s1), 1e-12f);
        nk[tid] = fmaxf(sqrtf(s2), 1e-12f);
    }
    __syncthreads();

    // B. normalize: attn = G / (||q_d|| * ||k_e||)
    for (int idx = tid; idx < 4096; idx += 256) {
        const int c = idx >> 6, e = idx & 63;
        X[c*65 + e] = X[c*65 + e] / (nq[c]*nk[e]);
    }
    __syncthreads();

    // C. gates (computed from pre-scaled attn, like the reference)
    if (tid < 64) {
        float a = 0.f;
        for (int c = 0; c < 64; c++) a += X[c*65 + tid]*col_w[c];
        wcol[tid] = 1.f/(1.f + expf(-(a + col_b[0])));
    } else if (tid < 128) {
        const int r = tid - 64;
        float a = 0.f;
        for (int e = 0; e < 64; e++) a += X[r*65 + e]*row_w[e];
        wrow[r] = 1.f/(1.f + expf(-(a + row_b[0])));
    }
    __syncthreads();

    // D. attn = attn*(wcol[e]+wrow[c])*temperature[h]
    const float tmp = temp[h];
    for (int idx = tid; idx < 4096; idx += 256) {
        const int c = idx >> 6, e = idx & 63;
        X[c*65 + e] *= (wcol[e] + wrow[c])*tmp;
    }
    __syncthreads();

    // E/F/G: fused 4x top-k masked softmax. 4 threads per row.
    const int r = tid >> 2, p = tid & 3;
    const int K0 = 32, K1 = 42, K2 = 48, K3 = 51; // C//2, 2C//3, 3C//4, 4C//5 for C=64
    {
        float m = -1e30f;
        for (int e = p*16; e < p*16 + 16; e++) m = fmaxf(m, X[r*65 + e]);
        pmax[r][p] = m;
    }
    __syncthreads();
    if (p == 0) rmax[r] = fmaxf(fmaxf(pmax[r][0], pmax[r][1]), fmaxf(pmax[r][2], pmax[r][3]));
    __syncthreads();
    {
        float z0 = 0.f, z1 = 0.f, z2 = 0.f, z3 = 0.f;
        const float rm = rmax[r];
        for (int e = p*16; e < p*16 + 16; e++) {
            const float xe = X[r*65 + e];
            int cnt = 0;
#pragma unroll
            for (int f = 0; f < 64; f++) cnt += (X[r*65 + f] > xe) ? 1 : 0;
            const float ex = expf(xe - rm);
            EX[r*65 + e] = ex;
            CNT[r*64 + e] = (unsigned char)cnt;
            if (cnt < K0) z0 += ex;
            if (cnt < K1) z1 += ex;
            if (cnt < K2) z2 += ex;
            if (cnt < K3) z3 += ex;
        }
        zps[r][p][0] = z0; zps[r][p][1] = z1; zps[r][p][2] = z2; zps[r][p][3] = z3;
    }
    __syncthreads();
    if (p == 0) {
#pragma unroll
        for (int i = 0; i < 4; i++) {
            const float Z = zps[r][0][i] + zps[r][1][i] + zps[r][2][i] + zps[r][3][i];
            coef[r][i] = attns[i]/Z;
        }
    }
    __syncthreads();
    {
        const float c0 = coef[r][0], c1 = coef[r][1], c2 = coef[r][2], c3 = coef[r][3];
        for (int e = p*16; e < p*16 + 16; e++) {
            const int cnt = CNT[r*64 + e];
            float val = 0.f;
            if (cnt < K0) val += c0;
            if (cnt < K1) val += c1;
            if (cnt < K2) val += c2;
            if (cnt < K3) val += c3;
            X[r*65 + e] = EX[r*65 + e]*val;
        }
    }
    __syncthreads();

    // H. write transposed, coalesced: At[e][c] = A[c][e]
    float* outp = g_At + (size_t)bh*4096;
    for (int idx = tid; idx < 4096; idx += 256) {
        const int e = idx >> 6, c = idx & 63;
        outp[idx] = X[c*65 + e];
    }
}

// ---------------------------------------------------------------------------
// Phase 3: out[b,l,h,d] = sum_e A[d,e]*v[b,l,h,e].
// Grid (BH, NLB), 256 threads; each block owns 160 l's (5 tiles of 32).
// ---------------------------------------------------------------------------
__global__ __launch_bounds__(256) void phase3_kernel(const float* __restrict__ v,
                                                     float* __restrict__ out)
{
    const int bh = blockIdx.x, lb = blockIdx.y;
    const int b = bh >> 3, h = bh & 7;
    const int tid = threadIdx.x;
    const int tx = tid & 15;   // d-group (4 d's)
    const int ty = tid >> 4;   // l index within tile (handles ty and ty+16)

    __shared__ float As[64*68];  // [e][c], row stride 68 (16B-aligned rows, no conflicts)
    __shared__ float vs[32*68];  // [l][e]

    const float* At = g_At + (size_t)bh*4096;
    for (int idx = tid; idx < 4096; idx += 256)
        As[(idx >> 6)*68 + (idx & 63)] = At[idx];

    const float* vbase = v   + (size_t)b*Ll*STRIDE_L + h*Dd;
    float*       obase = out + (size_t)b*Ll*STRIDE_L + h*Dd;
    const int l00 = lb*LBLOCK;

    for (int t = 0; t < TILES_PER_BLOCK; t++) {
        const int l0 = l00 + t*LT3;
        __syncthreads();
#pragma unroll
        for (int rep = 0; rep < 2; rep++) {
            const int fidx = tid + rep*256;
            const int lr = fidx >> 4, dgg = fidx & 15;
            float4 vv = *(const float4*)(vbase + (size_t)(l0 + lr)*STRIDE_L + dgg*4);
            *(float4*)&vs[lr*68 + dgg*4] = vv;
        }
        __syncthreads();

        float acc[4][2];
#pragma unroll
        for (int i = 0; i < 4; i++) { acc[i][0] = 0.f; acc[i][1] = 0.f; }

        const int la = ty, lbt = ty + 16;
#pragma unroll
        for (int e = 0; e < 64; e++) {
            float4 a = *(const float4*)&As[e*68 + tx*4];
            const float v0 = vs[la*68 + e];
            const float v1 = vs[lbt*68 + e];
            acc[0][0] += a.x*v0; acc[1][0] += a.y*v0; acc[2][0] += a.z*v0; acc[3][0] += a.w*v0;
            acc[0][1] += a.x*v1; acc[1][1] += a.y*v1; acc[2][1] += a.z*v1; acc[3][1] += a.w*v1;
        }

        float4 r0 = make_float4(acc[0][0], acc[1][0], acc[2][0], acc[3][0]);
        float4 r1 = make_float4(acc[0][1], acc[1][1], acc[2][1], acc[3][1]);
        *(float4*)(obase + (size_t)(l0 + la )*STRIDE_L + tx*4) = r0;
        *(float4*)(obase + (size_t)(l0 + lbt)*STRIDE_L + tx*4) = r1;
    }
}

// ---------------------------------------------------------------------------
extern "C" void kernel_launch(void* const* d_in, const int* in_sizes, int n_in,
                              void* d_out, int out_size)
{
    const float* q      = (const float*)d_in[0];
    const float* k      = (const float*)d_in[1];
    const float* v      = (const float*)d_in[2];
    const float* temp   = (const float*)d_in[3];
    const float* attns  = (const float*)d_in[4];
    const float* row_w  = (const float*)d_in[5];
    const float* row_b  = (const float*)d_in[6];
    const float* col_w  = (const float*)d_in[7];
    const float* col_b  = (const float*)d_in[8];
    float* out = (float*)d_out;

    phase1_kernel<<<dim3(BH, NSPLIT), 256>>>(q, k);
    phase2_kernel<<<BH, 256>>>(temp, attns, row_w, row_b, col_w, col_b);
    phase3_kernel<<<dim3(BH, NLB), 256>>>(v, out);
}

// round 2
// speedup vs baseline: 1.3243x; 1.3243x over previous
#include <cuda_runtime.h>
#include <math.h>

typedef unsigned long long ull;

// Problem dims (fixed by the dataset)
#define Bb 8
#define Ll 4800
#define Hh 8
#define Dd 64
#define BH (Bb*Hh)          // 64
#define STRIDE_L (Hh*Dd)    // 512 floats between consecutive l for fixed (b,h)

// Phase-1 split of L
#define NSPLIT 10
#define CHUNK (Ll/NSPLIT)   // 480
#define NT (CHUNK/16)       // 30 tiles of 16 l's

// Phase-3: one 128-l tile per block
#define NLB3 38             // ceil(4800/128)

// Scratch (static __device__ — no allocation in kernel_launch)
__device__ float g_Gp[NSPLIT*BH*Dd*Dd];   // partial Gram matrices [split][bh][d][e]
__device__ float g_Nqp[NSPLIT*BH*Dd];     // partial sum-of-squares for q norms
__device__ float g_Nkp[NSPLIT*BH*Dd];     // partial sum-of-squares for k norms
__device__ float g_At[BH*Dd*Dd];          // combined softmax matrix, TRANSPOSED: At[e][c] = A[c][e]

// ---- packed f32x2 helpers (FFMA2: 2 FMA lanes per instruction) -------------
__device__ __forceinline__ ull pack2(float lo, float hi){
    ull r; asm("mov.b64 %0, {%1, %2};" : "=l"(r) : "f"(lo), "f"(hi)); return r;
}
__device__ __forceinline__ ull ffma2(ull a, ull b, ull c){
    ull d; asm("fma.rn.f32x2 %0, %1, %2, %3;" : "=l"(d) : "l"(a), "l"(b), "l"(c)); return d;
}
__device__ __forceinline__ ull fadd2(ull a, ull b){
    ull d; asm("add.rn.f32x2 %0, %1, %2;" : "=l"(d) : "l"(a), "l"(b)); return d;
}
__device__ __forceinline__ float2 unpack2(ull v){
    float lo, hi; asm("mov.b64 {%0, %1}, %2;" : "=f"(lo), "=f"(hi) : "l"(v));
    return make_float2(lo, hi);
}

// ---------------------------------------------------------------------------
// Phase 1: partial Gram G[d,e] = sum_l q[l,d]*k[l,e] over an L-chunk,
// plus partial sum-of-squares per d.
// 256 threads = 4 L-slices x 64 compute threads; each compute thread owns an
// 8x8 output tile held as 8x4 f32x2 accumulators (pairs along e). Slices are
// reduced in registers+smem at the end. Global loads are register-prefetched.
// ---------------------------------------------------------------------------
__global__ __launch_bounds__(256) void phase1_kernel(const float* __restrict__ q,
                                                     const float* __restrict__ k)
{
    const int bh = blockIdx.x, sp = blockIdx.y;
    const int b = bh >> 3, h = bh & 7;
    const int tid = threadIdx.x;
    const int lrow = tid >> 4, lcol = (tid & 15) << 2;   // load layout
    const int sl = tid >> 6;                             // l-slice 0..3
    const int t64 = tid & 63;
    const int ty = t64 >> 3, tx = t64 & 7;               // 8x8 tile coords

    __shared__ float sm[2*64*66];   // 33.8KB: qs/ks during loop, reduction after
    float* qs = sm;
    float* ks = sm + 1024;

    ull acc[8][4];
#pragma unroll
    for (int i = 0; i < 8; i++)
#pragma unroll
        for (int j = 0; j < 4; j++) acc[i][j] = 0ull;

    float sq[4] = {0.f,0.f,0.f,0.f};
    float sk[4] = {0.f,0.f,0.f,0.f};

    const float* qb = q + (size_t)b*Ll*STRIDE_L + h*Dd;
    const float* kb = k + (size_t)b*Ll*STRIDE_L + h*Dd;
    const int l0 = sp*CHUNK;

    // prologue prefetch (tile 0)
    size_t off = (size_t)(l0 + lrow)*STRIDE_L + lcol;
    float4 vq = *(const float4*)(qb + off);
    float4 vk = *(const float4*)(kb + off);

    for (int t = 0; t < NT; t++) {
        *(float4*)&qs[lrow*64 + lcol] = vq;
        *(float4*)&ks[lrow*64 + lcol] = vk;
        sq[0] += vq.x*vq.x; sq[1] += vq.y*vq.y; sq[2] += vq.z*vq.z; sq[3] += vq.w*vq.w;
        sk[0] += vk.x*vk.x; sk[1] += vk.y*vk.y; sk[2] += vk.z*vk.z; sk[3] += vk.w*vk.w;
        __syncthreads();

        if (t + 1 < NT) {
            off = (size_t)(l0 + (t+1)*16 + lrow)*STRIDE_L + lcol;
            vq = *(const float4*)(qb + off);
            vk = *(const float4*)(kb + off);
        }

#pragma unroll
        for (int lls = 0; lls < 4; lls++) {
            const int ll = lls*4 + sl;
            const float4 a0 = *(const float4*)&qs[ll*64 + ty*8];
            const float4 a1 = *(const float4*)&qs[ll*64 + ty*8 + 4];
            const float4 b0 = *(const float4*)&ks[ll*64 + tx*8];
            const float4 b1 = *(const float4*)&ks[ll*64 + tx*8 + 4];
            const ull bp0 = pack2(b0.x, b0.y), bp1 = pack2(b0.z, b0.w);
            const ull bp2 = pack2(b1.x, b1.y), bp3 = pack2(b1.z, b1.w);
            const float av[8] = {a0.x,a0.y,a0.z,a0.w,a1.x,a1.y,a1.z,a1.w};
#pragma unroll
            for (int i = 0; i < 8; i++) {
                const ull ap = pack2(av[i], av[i]);
                acc[i][0] = ffma2(ap, bp0, acc[i][0]);
                acc[i][1] = ffma2(ap, bp1, acc[i][1]);
                acc[i][2] = ffma2(ap, bp2, acc[i][2]);
                acc[i][3] = ffma2(ap, bp3, acc[i][3]);
            }
        }
        __syncthreads();
    }

    // ---- cross-slice reduction (smem reused as two 64x66 staging tiles) ----
    float* red = sm;
    if (sl >= 2) {
        float* dst = red + (sl - 2)*64*66;
#pragma unroll
        for (int i = 0; i < 8; i++)
#pragma unroll
            for (int j = 0; j < 4; j++)
                *(ull*)&dst[(ty*8 + i)*66 + tx*8 + 2*j] = acc[i][j];
    }
    __syncthreads();
    if (sl < 2) {
        const float* src = red + sl*64*66;
#pragma unroll
        for (int i = 0; i < 8; i++)
#pragma unroll
            for (int j = 0; j < 4; j++)
                acc[i][j] = fadd2(acc[i][j], *(const ull*)&src[(ty*8 + i)*66 + tx*8 + 2*j]);
    }
    __syncthreads();
    if (sl == 1) {
#pragma unroll
        for (int i = 0; i < 8; i++)
#pragma unroll
            for (int j = 0; j < 4; j++)
                *(ull*)&red[(ty*8 + i)*66 + tx*8 + 2*j] = acc[i][j];
    }
    __syncthreads();
    if (sl == 0) {
        float* G = g_Gp + (size_t)(sp*BH + bh)*4096;
#pragma unroll
        for (int i = 0; i < 8; i++)
#pragma unroll
            for (int j = 0; j < 4; j++) {
                const ull r = fadd2(acc[i][j], *(const ull*)&red[(ty*8 + i)*66 + tx*8 + 2*j]);
                *(ull*)&G[(ty*8 + i)*64 + tx*8 + 2*j] = r;
            }
    }
    __syncthreads();

    // ---- sum-of-squares reduction (reuse sm[0..2047]) ----
    *(float4*)&sm[lrow*64 + lcol]        = make_float4(sq[0], sq[1], sq[2], sq[3]);
    *(float4*)&sm[1024 + lrow*64 + lcol] = make_float4(sk[0], sk[1], sk[2], sk[3]);
    __syncthreads();
    if (tid < 64) {
        float s1 = 0.f, s2 = 0.f;
#pragma unroll
        for (int r = 0; r < 16; r++) { s1 += sm[r*64 + tid]; s2 += sm[1024 + r*64 + tid]; }
        g_Nqp[(sp*BH + bh)*64 + tid] = s1;
        g_Nkp[(sp*BH + bh)*64 + tid] = s2;
    }
}

// ---------------------------------------------------------------------------
// Phase 2: per (b,h): assemble G, normalize, gates, temperature, and the four
// top-k masked softmaxes fused into one A_total matrix (stored transposed).
// Top-k membership: x_e >= (k-th largest)  <=>  #{f: x_f > x_e} < k.
// ---------------------------------------------------------------------------
__global__ __launch_bounds__(256) void phase2_kernel(
    const float* __restrict__ temp, const float* __restrict__ attns,
    const float* __restrict__ row_w, const float* __restrict__ row_b,
    const float* __restrict__ col_w, const float* __restrict__ col_b)
{
    const int bh = blockIdx.x;
    const int h  = bh & 7;
    const int tid = threadIdx.x;

    __shared__ float X[64*65];
    __shared__ float EX[64*65];
    __shared__ unsigned char CNT[64*64];
    __shared__ float nq[64], nk[64], wcol[64], wrow[64], rmax[64];
    __shared__ float pmax[64][4];
    __shared__ float zps[64][4][4];
    __shared__ float coef[64][4];

    for (int idx = tid; idx < 4096; idx += 256) {
        float s = 0.f;
#pragma unroll
        for (int sp = 0; sp < NSPLIT; sp++) s += g_Gp[(size_t)(sp*BH + bh)*4096 + idx];
        X[(idx >> 6)*65 + (idx & 63)] = s;
    }
    if (tid < 64) {
        float s1 = 0.f, s2 = 0.f;
#pragma unroll
        for (int sp = 0; sp < NSPLIT; sp++) {
            s1 += g_Nqp[(sp*BH + bh)*64 + tid];
            s2 += g_Nkp[(sp*BH + bh)*64 + tid];
        }
        nq[tid] = fmaxf(sqrtf(s1), 1e-12f);
        nk[tid] = fmaxf(sqrtf(s2), 1e-12f);
    }
    __syncthreads();

    for (int idx = tid; idx < 4096; idx += 256) {
        const int c = idx >> 6, e = idx & 63;
        X[c*65 + e] = X[c*65 + e] / (nq[c]*nk[e]);
    }
    __syncthreads();

    if (tid < 64) {
        float a = 0.f;
        for (int c = 0; c < 64; c++) a += X[c*65 + tid]*col_w[c];
        wcol[tid] = 1.f/(1.f + expf(-(a + col_b[0])));
    } else if (tid < 128) {
        const int r = tid - 64;
        float a = 0.f;
        for (int e = 0; e < 64; e++) a += X[r*65 + e]*row_w[e];
        wrow[r] = 1.f/(1.f + expf(-(a + row_b[0])));
    }
    __syncthreads();

    const float tmp = temp[h];
    for (int idx = tid; idx < 4096; idx += 256) {
        const int c = idx >> 6, e = idx & 63;
        X[c*65 + e] *= (wcol[e] + wrow[c])*tmp;
    }
    __syncthreads();

    const int r = tid >> 2, p = tid & 3;
    const int K0 = 32, K1 = 42, K2 = 48, K3 = 51;
    {
        float m = -1e30f;
        for (int e = p*16; e < p*16 + 16; e++) m = fmaxf(m, X[r*65 + e]);
        pmax[r][p] = m;
    }
    __syncthreads();
    if (p == 0) rmax[r] = fmaxf(fmaxf(pmax[r][0], pmax[r][1]), fmaxf(pmax[r][2], pmax[r][3]));
    __syncthreads();
    {
        float z0 = 0.f, z1 = 0.f, z2 = 0.f, z3 = 0.f;
        const float rm = rmax[r];
        for (int e = p*16; e < p*16 + 16; e++) {
            const float xe = X[r*65 + e];
            int cnt = 0;
#pragma unroll
            for (int f = 0; f < 64; f++) cnt += (X[r*65 + f] > xe) ? 1 : 0;
            const float ex = expf(xe - rm);
            EX[r*65 + e] = ex;
            CNT[r*64 + e] = (unsigned char)cnt;
            if (cnt < K0) z0 += ex;
            if (cnt < K1) z1 += ex;
            if (cnt < K2) z2 += ex;
            if (cnt < K3) z3 += ex;
        }
        zps[r][p][0] = z0; zps[r][p][1] = z1; zps[r][p][2] = z2; zps[r][p][3] = z3;
    }
    __syncthreads();
    if (p == 0) {
#pragma unroll
        for (int i = 0; i < 4; i++) {
            const float Z = zps[r][0][i] + zps[r][1][i] + zps[r][2][i] + zps[r][3][i];
            coef[r][i] = attns[i]/Z;
        }
    }
    __syncthreads();
    {
        const float c0 = coef[r][0], c1 = coef[r][1], c2 = coef[r][2], c3 = coef[r][3];
        for (int e = p*16; e < p*16 + 16; e++) {
            const int cnt = CNT[r*64 + e];
            float val = 0.f;
            if (cnt < K0) val += c0;
            if (cnt < K1) val += c1;
            if (cnt < K2) val += c2;
            if (cnt < K3) val += c3;
            X[r*65 + e] = EX[r*65 + e]*val;
        }
    }
    __syncthreads();

    float* outp = g_At + (size_t)bh*4096;
    for (int idx = tid; idx < 4096; idx += 256) {
        const int e = idx >> 6, c = idx & 63;
        outp[idx] = X[c*65 + e];
    }
}

// ---------------------------------------------------------------------------
// Phase 3: out[b,l,h,d] = sum_e A[d,e]*v[b,l,h,e].
// One 128-l tile per block, 256 threads, 4d x 8l per thread as 4x4 f32x2
// accumulators (pairs along l). v is staged TRANSPOSED vs[e][l] (swizzled so
// the scatter stores are only 4-way conflicted); A staged as As[e][d].
// ---------------------------------------------------------------------------
#define SV 132
__global__ __launch_bounds__(256) void phase3_kernel(const float* __restrict__ v,
                                                     float* __restrict__ out)
{
    const int bh = blockIdx.x, lt = blockIdx.y;
    const int b = bh >> 3, h = bh & 7;
    const int tid = threadIdx.x;
    const int tx = tid & 15, ty = tid >> 4;   // d-group, l-group
    const int l0 = lt * 128;

    __shared__ float As[64*68];
    __shared__ float vs[64*SV];

    const float* At = g_At + (size_t)bh*4096;
#pragma unroll
    for (int rr = 0; rr < 4; rr++) {
        const int idx4 = rr*256 + tid;
        const int e = idx4 >> 4, c4 = (idx4 & 15) << 2;
        *(float4*)&As[e*68 + c4] = *(const float4*)&At[e*64 + c4];
    }

    const float* vbase = v + (size_t)b*Ll*STRIDE_L + h*Dd;
#pragma unroll
    for (int rr = 0; rr < 8; rr++) {
        const int idx = rr*256 + tid;
        const int l = idx >> 4, eg = idx & 15;
        float4 vv = make_float4(0.f, 0.f, 0.f, 0.f);
        if (l0 + l < Ll) vv = *(const float4*)(vbase + (size_t)(l0 + l)*STRIDE_L + eg*4);
        const int lp = (l + 8*(eg & 3)) & 127;   // swizzle: shift rows by e-group
        const int eb = eg*4;
        vs[(eb+0)*SV + lp] = vv.x;
        vs[(eb+1)*SV + lp] = vv.y;
        vs[(eb+2)*SV + lp] = vv.z;
        vs[(eb+3)*SV + lp] = vv.w;
    }
    __syncthreads();

    ull acc[4][4];
#pragma unroll
    for (int i = 0; i < 4; i++)
#pragma unroll
        for (int j = 0; j < 4; j++) acc[i][j] = 0ull;

    const int lbase = ty*8;
#pragma unroll
    for (int e = 0; e < 64; e++) {
        const float4 a4 = *(const float4*)&As[e*68 + tx*4];
        const int lp = (lbase + 8*((e >> 2) & 3)) & 127;
        const float4 v0 = *(const float4*)&vs[e*SV + lp];
        const float4 v1 = *(const float4*)&vs[e*SV + lp + 4];
        const ull vp0 = pack2(v0.x, v0.y), vp1 = pack2(v0.z, v0.w);
        const ull vp2 = pack2(v1.x, v1.y), vp3 = pack2(v1.z, v1.w);
        const float aa[4] = {a4.x, a4.y, a4.z, a4.w};
#pragma unroll
        for (int i = 0; i < 4; i++) {
            const ull ap = pack2(aa[i], aa[i]);
            acc[i][0] = ffma2(ap, vp0, acc[i][0]);
            acc[i][1] = ffma2(ap, vp1, acc[i][1]);
            acc[i][2] = ffma2(ap, vp2, acc[i][2]);
            acc[i][3] = ffma2(ap, vp3, acc[i][3]);
        }
    }

    float* obase = out + (size_t)b*Ll*STRIDE_L + h*Dd;
#pragma unroll
    for (int j = 0; j < 4; j++) {
        const float2 u0 = unpack2(acc[0][j]);
        const float2 u1 = unpack2(acc[1][j]);
        const float2 u2 = unpack2(acc[2][j]);
        const float2 u3 = unpack2(acc[3][j]);
        const int l = l0 + lbase + 2*j;
        if (l < Ll)
            *(float4*)(obase + (size_t)l*STRIDE_L + tx*4)     = make_float4(u0.x, u1.x, u2.x, u3.x);
        if (l + 1 < Ll)
            *(float4*)(obase + (size_t)(l+1)*STRIDE_L + tx*4) = make_float4(u0.y, u1.y, u2.y, u3.y);
    }
}

// ---------------------------------------------------------------------------
extern "C" void kernel_launch(void* const* d_in, const int* in_sizes, int n_in,
                              void* d_out, int out_size)
{
    const float* q      = (const float*)d_in[0];
    const float* k      = (const float*)d_in[1];
    const float* v      = (const float*)d_in[2];
    const float* temp   = (const float*)d_in[3];
    const float* attns  = (const float*)d_in[4];
    const float* row_w  = (const float*)d_in[5];
    const float* row_b  = (const float*)d_in[6];
    const float* col_w  = (const float*)d_in[7];
    const float* col_b  = (const float*)d_in[8];
    float* out = (float*)d_out;

    phase1_kernel<<<dim3(BH, NSPLIT), 256>>>(q, k);
    phase2_kernel<<<BH, 256>>>(temp, attns, row_w, row_b, col_w, col_b);
    phase3_kernel<<<dim3(BH, NLB3), 256>>>(v, out);
}